// round 1
// baseline (speedup 1.0000x reference)
#include <cuda_runtime.h>

// Problem constants
constexpr int PB = 2;      // batch
constexpr int PC = 64;     // feature channels
constexpr int PH = 256;
constexpr int PW = 256;
constexpr int CH = 32;
constexpr int IMG = 512;

// Scratch (device globals; no allocation allowed)
__device__ float g_E[PB * PC * PH * PW];   // embedding [b][c][h][w], 33.5 MB
__device__ float g_S[PB * PH * PW];        // inp . w_comp map
__device__ float g_PX[CH * PW];            // pos embd, x-part [o][w]
__device__ float g_PY[CH * PH];            // pos embd, y-part [o][h]

// ---------------------------------------------------------------------------
// K1: positional tables.  PX[o][w] = sum_i w_pos[o][2i]*sin(w*div_i) + w_pos[o][2i+1]*cos(w*div_i)
//     PY[o][h] = same with w_pos[o][32+...]
// ---------------------------------------------------------------------------
__global__ void pos_kernel(const float* __restrict__ w_pos) {
    int idx = blockIdx.x * blockDim.x + threadIdx.x;   // 0..16383
    if (idx >= 2 * CH * 256) return;
    int half = idx >> 13;            // 0 = PX, 1 = PY
    int o = (idx >> 8) & 31;
    int p = idx & 255;
    const float kexp = -0.28782313662425575f;  // -ln(10000)/32
    int cbase = half ? 32 : 0;
    float acc = 0.f;
#pragma unroll
    for (int i = 0; i < 16; i++) {
        float dv = __expf((float)(2 * i) * kexp);
        float s, c;
        __sincosf((float)p * dv, &s, &c);
        acc += w_pos[o * 64 + cbase + 2 * i] * s + w_pos[o * 64 + cbase + 2 * i + 1] * c;
    }
    if (half == 0) g_PX[o * 256 + p] = acc;
    else           g_PY[o * 256 + p] = acc;
}

// ---------------------------------------------------------------------------
// K2: build E and S.
//  jax.image.resize bilinear (antialias) 512->256: 4 taps per axis,
//  interior weights {1/8,3/8,3/8,1/8}, borders renormalized {3/7,3/7,1/7}.
// ---------------------------------------------------------------------------
__device__ __forceinline__ void make_taps(int o, int* j, float* wt) {
    j[0] = 2 * o - 1; j[1] = 2 * o; j[2] = 2 * o + 1; j[3] = 2 * o + 2;
    wt[0] = 0.125f; wt[1] = 0.375f; wt[2] = 0.375f; wt[3] = 0.125f;
    if (o == 0) {
        j[0] = 0; wt[0] = 0.f;
        wt[1] = 3.f / 7.f; wt[2] = 3.f / 7.f; wt[3] = 1.f / 7.f;
    } else if (o == 255) {
        j[3] = 511; wt[3] = 0.f;
        wt[0] = 1.f / 7.f; wt[1] = 3.f / 7.f; wt[2] = 3.f / 7.f;
    }
}

__global__ __launch_bounds__(256) void e_kernel(
    const float* __restrict__ inp, const float* __restrict__ img,
    const float* __restrict__ w_img, const float* __restrict__ w_comp)
{
    int idx = blockIdx.x * blockDim.x + threadIdx.x;   // 0..131071
    int b = idx >> 16;
    int h = (idx >> 8) & 255;
    int w = idx & 255;

    int jh[4], jw[4]; float wh[4], ww[4];
    make_taps(h, jh, wh);
    make_taps(w, jw, ww);

    float r[3];
#pragma unroll
    for (int c = 0; c < 3; c++) {
        const float* ip = img + (b * 3 + c) * IMG * IMG;
        float acc = 0.f;
#pragma unroll
        for (int a = 0; a < 4; a++) {
            float row = 0.f;
#pragma unroll
            for (int t = 0; t < 4; t++) row += ww[t] * ip[jh[a] * IMG + jw[t]];
            acc += wh[a] * row;
        }
        r[c] = acc;
    }

    int base = b * PC * PH * PW + h * PW + w;
#pragma unroll
    for (int o = 0; o < 32; o++) {
        g_E[base + o * (PH * PW)] =
            w_img[o * 3 + 0] * r[0] + w_img[o * 3 + 1] * r[1] + w_img[o * 3 + 2] * r[2];
        g_E[base + (32 + o) * (PH * PW)] = g_PX[o * 256 + w] + g_PY[o * 256 + h];
    }

    // S = inp . w_comp over channels
    const float* ip2 = inp + b * PC * PH * PW + h * PW + w;
    float s = 0.f;
#pragma unroll
    for (int c = 0; c < PC; c++) s += w_comp[c] * ip2[c * (PH * PW)];
    g_S[b * PH * PW + h * PW + w] = s;
}

// ---------------------------------------------------------------------------
// K3: main fused kernel.  Tile 32(w) x 8(h), 1 pixel per thread.
//  Phase 1: feature_score over E (16-ch smem chunks, zero-filled halo).
//  Phase 2: phi_k = fs_k * sigmoid(S[neighbor]).
//  Phase 3: out[c] = sum_k phi_k * inp[c, neighbor] (same smem buffer).
// ---------------------------------------------------------------------------
constexpr int TW = 32, TH = 8;
constexpr int SW = TW + 4, SH = TH + 4;   // 36 x 12 halo tile
constexpr int CCH = 16;                   // channels per smem chunk

__global__ __launch_bounds__(256) void main_kernel(
    const float* __restrict__ inp, float* __restrict__ out)
{
    const int b  = blockIdx.z;
    const int h0 = blockIdx.y * TH;
    const int w0 = blockIdx.x * TW;
    const int tid = threadIdx.x;
    const int tx = tid & 31;
    const int ty = tid >> 5;      // 0..7

    __shared__ float sT[CCH][SH][SW];
    __shared__ float sS[SH][SW];

    // load S tile (zero-filled halo)
    for (int i = tid; i < SH * SW; i += 256) {
        int r = i / SW, c2 = i % SW;
        int gh = h0 - 2 + r, gw = w0 - 2 + c2;
        float v = 0.f;
        if ((unsigned)gh < PH && (unsigned)gw < PW) v = g_S[(b * PH + gh) * PW + gw];
        sS[r][c2] = v;
    }

    float fs[9];
#pragma unroll
    for (int k = 0; k < 9; k++) fs[k] = 0.f;

    // Phase 1: feature score
    for (int ch0 = 0; ch0 < PC; ch0 += CCH) {
        __syncthreads();
        for (int i = tid; i < CCH * SH * SW; i += 256) {
            int c = i / (SH * SW);
            int rem = i % (SH * SW);
            int r = rem / SW, cc = rem % SW;
            int gh = h0 - 2 + r, gw = w0 - 2 + cc;
            float v = 0.f;
            if ((unsigned)gh < PH && (unsigned)gw < PW)
                v = g_E[((b * PC + ch0 + c) * PH + gh) * PW + gw];
            sT[c][r][cc] = v;
        }
        __syncthreads();
#pragma unroll
        for (int c = 0; c < CCH; c++) {
            float ctr = sT[c][ty + 2][tx + 2];
#pragma unroll
            for (int k = 0; k < 9; k++) {
                int di = (k / 3) * 2, dj = (k % 3) * 2;
                fs[k] += sT[c][ty + di][tx + dj] * ctr;
            }
        }
    }

    // Phase 2: phi = fs * sigmoid(S_neighbor).  Zero halo => fs==0 kills OOB terms.
    float phi[9];
#pragma unroll
    for (int k = 0; k < 9; k++) {
        int di = (k / 3) * 2, dj = (k % 3) * 2;
        float s = sS[ty + di][tx + dj];
        phi[k] = fs[k] * (1.f / (1.f + __expf(-s)));
    }

    // Phase 3: weighted feature aggregation
    for (int ch0 = 0; ch0 < PC; ch0 += CCH) {
        __syncthreads();
        for (int i = tid; i < CCH * SH * SW; i += 256) {
            int c = i / (SH * SW);
            int rem = i % (SH * SW);
            int r = rem / SW, cc = rem % SW;
            int gh = h0 - 2 + r, gw = w0 - 2 + cc;
            float v = 0.f;
            if ((unsigned)gh < PH && (unsigned)gw < PW)
                v = inp[((b * PC + ch0 + c) * PH + gh) * PW + gw];
            sT[c][r][cc] = v;
        }
        __syncthreads();
#pragma unroll
        for (int c = 0; c < CCH; c++) {
            float acc = 0.f;
#pragma unroll
            for (int k = 0; k < 9; k++) {
                int di = (k / 3) * 2, dj = (k % 3) * 2;
                acc += phi[k] * sT[c][ty + di][tx + dj];
            }
            out[((b * PC + ch0 + c) * PH + (h0 + ty)) * PW + (w0 + tx)] = acc;
        }
    }
}

// ---------------------------------------------------------------------------
extern "C" void kernel_launch(void* const* d_in, const int* in_sizes, int n_in,
                              void* d_out, int out_size)
{
    const float* inp    = (const float*)d_in[0];   // [2,64,256,256]
    const float* img    = (const float*)d_in[1];   // [2,3,512,512]
    const float* w_pos  = (const float*)d_in[2];   // [32,64]
    const float* w_img  = (const float*)d_in[3];   // [32,3]
    const float* w_comp = (const float*)d_in[4];   // [64]
    float* out = (float*)d_out;

    pos_kernel<<<64, 256>>>(w_pos);
    e_kernel<<<(PB * PH * PW) / 256, 256>>>(inp, img, w_img, w_comp);
    dim3 grid(PW / TW, PH / TH, PB);
    main_kernel<<<grid, 256>>>(inp, out);
}